// round 16
// baseline (speedup 1.0000x reference)
#include <cuda_runtime.h>
#include <cuda_bf16.h>
#include <cstdint>

#define NN 50000
#define NE 640000
#define DD 128
#define NTILE (NE / 128)   // 5000

// ---------------- device scratch --------------------------------------------
__device__ float g_A[NN * DD];     // node_h @ We1[0:128]
__device__ float g_B[NN * DD];     // node_h @ We1[128:256]
__device__ float g_agg[NN * DD];   // segment_sum(relu_hidden)
__device__ float g_aggm[NN * DD];  // agg @ We2 + deg*be2
__device__ float g_hid[NN * DD];
__device__ float g_deg[NN];
// 7 weight slices, hi/lo bf16, stored [n][k] (k contiguous)
__device__ __nv_bfloat16 g_Whi[7 * DD * DD];
__device__ __nv_bfloat16 g_Wlo[7 * DD * DD];

// ---------------- smem layout ------------------------------------------------
// Buffers of 128x64 bf16 with row stride SA=72 (144B: conflict-free ldmatrix).
// Convention: a "pair" is hi at <off>, lo at <off>+AB.
#define SA 72
#define AB 18432                    // 128*72*2 bytes per buffer
// tgemm: A pair at 0, W pair at 2AB
#define SMEM_T (4*AB + 1024)        // 74752
// edge (persistent): W chunk0 pair at 0, W chunk1 pair at 2AB, A pair at 4AB, idx at 6AB
#define SMEM_E (6*AB + 1024)        // 111616

// ---------------- helpers ----------------------------------------------------
__device__ __forceinline__ uint32_t smem_u32(const void* p) {
    uint32_t a;
    asm("{ .reg .u64 t; cvta.to.shared.u64 t, %1; cvt.u32.u64 %0, t; }" : "=r"(a) : "l"(p));
    return a;
}
__device__ __forceinline__ void ldm4(uint32_t* r, uint32_t a) {
    asm volatile("ldmatrix.sync.aligned.m8n8.x4.shared.b16 {%0,%1,%2,%3}, [%4];"
        : "=r"(r[0]), "=r"(r[1]), "=r"(r[2]), "=r"(r[3]) : "r"(a));
}
__device__ __forceinline__ void mmabf(float* c, const uint32_t* a, uint32_t b0, uint32_t b1) {
    asm volatile("mma.sync.aligned.m16n8k16.row.col.f32.bf16.bf16.f32 "
        "{%0,%1,%2,%3}, {%4,%5,%6,%7}, {%8,%9}, {%0,%1,%2,%3};"
        : "+f"(c[0]), "+f"(c[1]), "+f"(c[2]), "+f"(c[3])
        : "r"(a[0]), "r"(a[1]), "r"(a[2]), "r"(a[3]), "r"(b0), "r"(b1));
}
__device__ __forceinline__ void red2(float* p, float x, float y) {
    asm volatile("red.global.add.v2.f32 [%0], {%1,%2};" :: "l"(p), "f"(x), "f"(y) : "memory");
}

// ---------------- small kernels ----------------------------------------------
__global__ void zero_kernel() {
    int i = blockIdx.x * blockDim.x + threadIdx.x;
    int stride = gridDim.x * blockDim.x;
    float4 z = make_float4(0.f, 0.f, 0.f, 0.f);
    for (int j = i; j < NN * DD / 4; j += stride) ((float4*)g_agg)[j] = z;
    for (int j = i; j < NN; j += stride) g_deg[j] = 0.f;
}

// split each weight slice into hi/lo bf16, transposed to [n][k]
__global__ void prep_kernel(const float* __restrict__ We1, const float* __restrict__ We2,
                            const float* __restrict__ Wn1, const float* __restrict__ Wn2) {
    int idx = blockIdx.x * blockDim.x + threadIdx.x;
    if (idx >= 7 * DD * DD) return;
    int s = idx >> 14, r = idx & 16383, k = r >> 7, n = r & 127;
    const float* base;
    switch (s) {
        case 0: base = We1;               break;
        case 1: base = We1 + DD * DD;     break;
        case 2: base = We1 + 2 * DD * DD; break;
        case 3: base = We2;               break;
        case 4: base = Wn1;               break;
        case 5: base = Wn1 + DD * DD;     break;
        default: base = Wn2;              break;
    }
    float w = base[k * DD + n];
    __nv_bfloat16 h = __float2bfloat16(w);
    __nv_bfloat16 l = __float2bfloat16(w - __bfloat162float(h));
    g_Whi[s * 16384 + n * DD + k] = h;
    g_Wlo[s * 16384 + n * DD + k] = l;
}

// ---------------- building blocks --------------------------------------------
// convert a [128 rows][64 k] fp32 chunk into hi/lo bf16 smem pair at aOff
__device__ __forceinline__ void convert_chunk(char* sm, int aOff, const float* __restrict__ X,
                                              int row0, int kc, int M, int tid, bool guard) {
    #pragma unroll
    for (int i = 0; i < 8; i++) {
        int f = i * 256 + tid;
        int row = f >> 4, k4 = (f & 15) * 4;
        float4 v = make_float4(0.f, 0.f, 0.f, 0.f);
        if (!guard || (row0 + row) < M)
            v = *(const float4*)(X + (size_t)(row0 + row) * DD + kc + k4);
        __nv_bfloat16 h0 = __float2bfloat16(v.x), h1 = __float2bfloat16(v.y);
        __nv_bfloat16 h2 = __float2bfloat16(v.z), h3 = __float2bfloat16(v.w);
        __nv_bfloat16 l0 = __float2bfloat16(v.x - __bfloat162float(h0));
        __nv_bfloat16 l1 = __float2bfloat16(v.y - __bfloat162float(h1));
        __nv_bfloat16 l2 = __float2bfloat16(v.z - __bfloat162float(h2));
        __nv_bfloat16 l3 = __float2bfloat16(v.w - __bfloat162float(h3));
        uint2 hp, lp;
        hp.x = ((uint32_t)__bfloat16_as_ushort(h1) << 16) | __bfloat16_as_ushort(h0);
        hp.y = ((uint32_t)__bfloat16_as_ushort(h3) << 16) | __bfloat16_as_ushort(h2);
        lp.x = ((uint32_t)__bfloat16_as_ushort(l1) << 16) | __bfloat16_as_ushort(l0);
        lp.y = ((uint32_t)__bfloat16_as_ushort(l3) << 16) | __bfloat16_as_ushort(l2);
        int off = (row * SA + k4) * 2;
        *(uint2*)(sm + aOff + off) = hp;
        *(uint2*)(sm + aOff + AB + off) = lp;
    }
}

// copy a [128 n][64 k] weight chunk (hi/lo) from global into smem pair at wOff
__device__ __forceinline__ void copyW_chunk(char* sm, int wOff,
                                            const __nv_bfloat16* __restrict__ ghi,
                                            const __nv_bfloat16* __restrict__ glo,
                                            int kc, int tid) {
    #pragma unroll
    for (int i = 0; i < 8; i++) {
        int idx = i * 256 + tid;
        int n = idx >> 4, j = (idx & 15) * 4;
        int off = (n * SA + j) * 2;
        *(uint2*)(sm + wOff + off) = *(const uint2*)(ghi + n * DD + kc + j);
        *(uint2*)(sm + wOff + AB + off) = *(const uint2*)(glo + n * DD + kc + j);
    }
}

// K=64 chunk of the bf16x3 warp MMA: terms AhBh, AlBh, AhBl
__device__ __forceinline__ void mma_chunk64(uint32_t sb, float C[4][4][4], int lane,
                                            int wm, int wn, int aOff, int wOff) {
    uint32_t aH = sb + aOff + (((wm * 64 + (lane & 15)) * SA) + (lane >> 4) * 8) * 2;
    uint32_t bRow = wn * 32 + (lane & 7) + ((lane >> 4) << 3);
    uint32_t bH = sb + wOff + ((bRow * SA) + ((lane >> 3) & 1) * 8) * 2;
    #pragma unroll
    for (int kk = 0; kk < 64; kk += 16) {
        uint32_t ah[4][4], bh[2][4];
        #pragma unroll
        for (int mf = 0; mf < 4; mf++) ldm4(ah[mf], aH + mf * (16 * SA * 2) + kk * 2);
        #pragma unroll
        for (int n2 = 0; n2 < 2; n2++) ldm4(bh[n2], bH + n2 * (16 * SA * 2) + kk * 2);
        #pragma unroll
        for (int mf = 0; mf < 4; mf++)
            #pragma unroll
            for (int nf = 0; nf < 4; nf++)
                mmabf(C[mf][nf], ah[mf], bh[nf >> 1][(nf & 1) * 2], bh[nf >> 1][(nf & 1) * 2 + 1]);
        {   // Al x Bh (reuse bh, fresh al regs)
            uint32_t al[4][4];
            #pragma unroll
            for (int mf = 0; mf < 4; mf++) ldm4(al[mf], aH + AB + mf * (16 * SA * 2) + kk * 2);
            #pragma unroll
            for (int mf = 0; mf < 4; mf++)
                #pragma unroll
                for (int nf = 0; nf < 4; nf++)
                    mmabf(C[mf][nf], al[mf], bh[nf >> 1][(nf & 1) * 2], bh[nf >> 1][(nf & 1) * 2 + 1]);
        }
        {   // Ah x Bl (overwrite bh with bl)
            #pragma unroll
            for (int n2 = 0; n2 < 2; n2++) ldm4(bh[n2], bH + AB + n2 * (16 * SA * 2) + kk * 2);
            #pragma unroll
            for (int mf = 0; mf < 4; mf++)
                #pragma unroll
                for (int nf = 0; nf < 4; nf++)
                    mmabf(C[mf][nf], ah[mf], bh[nf >> 1][(nf & 1) * 2], bh[nf >> 1][(nf & 1) * 2 + 1]);
        }
    }
}

// ---------------- node-side GEMM ---------------------------------------------
// MODE 0: out=X@W   1: +bias   2: relu(+bias)   3: +deg*bias
// NC: number of K=64 chunks (2 for K=128, 4 for K=256 concat [X1,X2])
template<int MODE, int NC>
__global__ __launch_bounds__(256, 2)
void tgemm(const float* __restrict__ X1, const float* __restrict__ X2,
           const __nv_bfloat16* __restrict__ whi, const __nv_bfloat16* __restrict__ wlo,
           const float* __restrict__ bias, float* __restrict__ out, int M) {
    extern __shared__ char sm[];
    uint32_t sb = smem_u32(sm);
    int tid = threadIdx.x, lane = tid & 31, wid = tid >> 5;
    int wm = wid & 1, wn = wid >> 1;
    int row0 = blockIdx.x * 128;

    float C[4][4][4];
    #pragma unroll
    for (int a = 0; a < 4; a++)
        #pragma unroll
        for (int b = 0; b < 4; b++)
            #pragma unroll
            for (int c = 0; c < 4; c++) C[a][b][c] = 0.f;

    #pragma unroll
    for (int c = 0; c < NC; c++) {
        if (c) __syncthreads();
        const float* X = (NC == 4 && c >= 2) ? X2 : X1;
        int kc = (c & 1) * 64;
        convert_chunk(sm, 0, X, row0, kc, M, tid, true);
        copyW_chunk(sm, 2 * AB, whi + (c >> 1) * 16384, wlo + (c >> 1) * 16384, kc, tid);
        __syncthreads();
        mma_chunk64(sb, C, lane, wm, wn, 0, 2 * AB);
    }

    int rl = lane >> 2, colb = wn * 32 + (lane & 3) * 2;
    float2 bz[4];
    if (MODE != 0) {
        #pragma unroll
        for (int nf = 0; nf < 4; nf++) bz[nf] = *(const float2*)(bias + colb + nf * 8);
    }
    #pragma unroll
    for (int mf = 0; mf < 4; mf++) {
        int ra = row0 + wm * 64 + mf * 16 + rl;
        #pragma unroll
        for (int h = 0; h < 2; h++) {
            int gr = ra + h * 8;
            if (gr >= M) continue;
            float dg = (MODE == 3) ? g_deg[gr] : 0.f;
            #pragma unroll
            for (int nf = 0; nf < 4; nf++) {
                int cc = colb + nf * 8;
                float o0 = C[mf][nf][h * 2 + 0];
                float o1 = C[mf][nf][h * 2 + 1];
                if (MODE == 1 || MODE == 2) { o0 += bz[nf].x; o1 += bz[nf].y; }
                if (MODE == 3) { o0 += dg * bz[nf].x; o1 += dg * bz[nf].y; }
                if (MODE == 2) { o0 = fmaxf(o0, 0.f); o1 = fmaxf(o1, 0.f); }
                *(float2*)(out + (size_t)gr * DD + cc) = make_float2(o0, o1);
            }
        }
    }
}

// ---------------- persistent edge kernel --------------------------------------
// hidden = relu(edge_h@We1c + A[src] + B[dst] + be1); red.add into g_agg[dst].
// W (We1c hi/lo, both K-chunks) resident in smem for the whole kernel.
__global__ __launch_bounds__(256, 2)
void edge_hmma(const float* __restrict__ edge_h, const int* __restrict__ src,
               const int* __restrict__ dst, const __nv_bfloat16* __restrict__ whi,
               const __nv_bfloat16* __restrict__ wlo, const float* __restrict__ be1) {
    extern __shared__ char sm[];
    uint32_t sb = smem_u32(sm);
    int tid = threadIdx.x, lane = tid & 31, wid = tid >> 5;
    int wm = wid & 1, wn = wid >> 1;
    int* se = (int*)(sm + 6 * AB);
    int* de = se + 128;

    // load both W chunks once (chunk c: hi at c*2AB, lo at c*2AB+AB)
    copyW_chunk(sm, 0,      whi, wlo, 0,  tid);
    copyW_chunk(sm, 2 * AB, whi, wlo, 64, tid);

    int rl = lane >> 2, colb = wn * 32 + (lane & 3) * 2;
    float2 be[4];
    #pragma unroll
    for (int nf = 0; nf < 4; nf++) be[nf] = *(const float2*)(be1 + colb + nf * 8);

    for (int tile = blockIdx.x; tile < NTILE; tile += gridDim.x) {
        __syncthreads();   // prior epilogue done before overwriting idx/A; also orders W load
        int e0 = tile * 128;
        if (tid < 128) { se[tid] = src[e0 + tid]; de[tid] = dst[e0 + tid]; }

        float C[4][4][4];
        #pragma unroll
        for (int a = 0; a < 4; a++)
            #pragma unroll
            for (int b = 0; b < 4; b++)
                #pragma unroll
                for (int c = 0; c < 4; c++) C[a][b][c] = 0.f;

        convert_chunk(sm, 4 * AB, edge_h, e0, 0, NE, tid, false);
        __syncthreads();
        mma_chunk64(sb, C, lane, wm, wn, 4 * AB, 0);
        __syncthreads();
        convert_chunk(sm, 4 * AB, edge_h, e0, 64, NE, tid, false);
        __syncthreads();
        mma_chunk64(sb, C, lane, wm, wn, 4 * AB, 2 * AB);

        #pragma unroll
        for (int mf = 0; mf < 4; mf++) {
            int rbase = wm * 64 + mf * 16 + rl;
            #pragma unroll
            for (int h = 0; h < 2; h++) {
                int row = rbase + h * 8;
                int s = se[row], d = de[row];
                const float* ag = g_A + (size_t)s * DD;
                const float* bg = g_B + (size_t)d * DD;
                float* agp = g_agg + (size_t)d * DD;
                #pragma unroll
                for (int nf = 0; nf < 4; nf++) {
                    int cc = colb + nf * 8;
                    float2 av = *(const float2*)(ag + cc);
                    float2 bv = *(const float2*)(bg + cc);
                    float o0 = C[mf][nf][h * 2 + 0] + av.x + bv.x + be[nf].x;
                    float o1 = C[mf][nf][h * 2 + 1] + av.y + bv.y + be[nf].y;
                    o0 = fmaxf(o0, 0.f); o1 = fmaxf(o1, 0.f);
                    red2(agp + cc, o0, o1);
                }
            }
        }
        // in-degree (each row counted exactly once: wn==0 warps, one lane per row)
        if (wn == 0 && (lane & 3) == 0) {
            #pragma unroll
            for (int mf = 0; mf < 4; mf++) {
                atomicAdd(&g_deg[de[wm * 64 + mf * 16 + rl]], 1.0f);
                atomicAdd(&g_deg[de[wm * 64 + mf * 16 + rl + 8]], 1.0f);
            }
        }
    }
}

// ---------------- launch -----------------------------------------------------
extern "C" void kernel_launch(void* const* d_in, const int* in_sizes, int n_in,
                              void* d_out, int out_size) {
    const float* node_h = (const float*)d_in[0];
    const float* edge_h = (const float*)d_in[1];
    const int*   src    = (const int*)d_in[2];
    const int*   dst    = (const int*)d_in[3];
    const float* We1    = (const float*)d_in[4];
    const float* be1    = (const float*)d_in[5];
    const float* We2    = (const float*)d_in[6];
    const float* be2    = (const float*)d_in[7];
    const float* Wn1    = (const float*)d_in[8];
    const float* bn1    = (const float*)d_in[9];
    const float* Wn2    = (const float*)d_in[10];
    const float* bn2    = (const float*)d_in[11];
    float* out = (float*)d_out;

    float *pA, *pB, *pAgg, *pAggm, *pHid;
    __nv_bfloat16 *pWhi, *pWlo;
    cudaGetSymbolAddress((void**)&pA,    g_A);
    cudaGetSymbolAddress((void**)&pB,    g_B);
    cudaGetSymbolAddress((void**)&pAgg,  g_agg);
    cudaGetSymbolAddress((void**)&pAggm, g_aggm);
    cudaGetSymbolAddress((void**)&pHid,  g_hid);
    cudaGetSymbolAddress((void**)&pWhi,  g_Whi);
    cudaGetSymbolAddress((void**)&pWlo,  g_Wlo);

    cudaFuncSetAttribute(tgemm<0,2>, cudaFuncAttributeMaxDynamicSharedMemorySize, SMEM_T);
    cudaFuncSetAttribute(tgemm<1,2>, cudaFuncAttributeMaxDynamicSharedMemorySize, SMEM_T);
    cudaFuncSetAttribute(tgemm<2,4>, cudaFuncAttributeMaxDynamicSharedMemorySize, SMEM_T);
    cudaFuncSetAttribute(tgemm<3,2>, cudaFuncAttributeMaxDynamicSharedMemorySize, SMEM_T);
    cudaFuncSetAttribute(edge_hmma,  cudaFuncAttributeMaxDynamicSharedMemorySize, SMEM_E);

    int nblk = (NN + 127) / 128;   // 391

    prep_kernel<<<(7 * DD * DD + 255) / 256, 256>>>(We1, We2, Wn1, Wn2);
    zero_kernel<<<296, 256>>>();
    // g_A = node_h @ We1a ; g_B = node_h @ We1b
    tgemm<0,2><<<nblk, 256, SMEM_T>>>(node_h, nullptr, pWhi + 0 * 16384, pWlo + 0 * 16384, nullptr, pA, NN);
    tgemm<0,2><<<nblk, 256, SMEM_T>>>(node_h, nullptr, pWhi + 1 * 16384, pWlo + 1 * 16384, nullptr, pB, NN);
    // edge: hidden = relu(edge_h@We1c + A[src] + B[dst] + be1) -> red into g_agg[dst]
    edge_hmma<<<296, 256, SMEM_E>>>(edge_h, src, dst, pWhi + 2 * 16384, pWlo + 2 * 16384, be1);
    // aggm = agg @ We2 + deg*be2
    tgemm<3,2><<<nblk, 256, SMEM_T>>>(pAgg, nullptr, pWhi + 3 * 16384, pWlo + 3 * 16384, be2, pAggm, NN);
    // hid = relu([aggm, node_h] @ Wn1 + bn1)
    tgemm<2,4><<<nblk, 256, SMEM_T>>>(pAggm, node_h, pWhi + 4 * 16384, pWlo + 4 * 16384, bn1, pHid, NN);
    // out = hid @ Wn2 + bn2
    tgemm<1,2><<<nblk, 256, SMEM_T>>>(pHid, nullptr, pWhi + 6 * 16384, pWlo + 6 * 16384, bn2, out, NN);
}